// round 12
// baseline (speedup 1.0000x reference)
#include <cuda_runtime.h>
#include <cstdint>

#define EPS 1e-5f
#define Nn 8
#define Cc 256
#define Hh 64
#define Ww 64
#define HW 4096
#define OC 64
#define Pp 36

typedef unsigned long long u64;
typedef unsigned int u32;
typedef unsigned short u16;

__device__ __forceinline__ u64 pack2(float x, float y) {
    u64 r; asm("mov.b64 %0, {%1,%2};" : "=l"(r) : "f"(x), "f"(y)); return r;
}
__device__ __forceinline__ void fma2(u64 &d, u64 a, u64 b) {
    asm("fma.rn.f32x2 %0, %1, %2, %0;" : "+l"(d) : "l"(a), "l"(b));
}
__device__ __forceinline__ float2 unpack2(u64 v) {
    float2 r; asm("mov.b64 {%0,%1}, %2;" : "=f"(r.x), "=f"(r.y) : "l"(v)); return r;
}
__device__ __forceinline__ u32 smem_u32(const void* p) {
    u32 a;
    asm("{ .reg .u64 t; cvta.to.shared.u64 t, %1; cvt.u32.u64 %0, t; }" : "=r"(a) : "l"(p));
    return a;
}
__device__ __forceinline__ void ldsm4(u32& r0, u32& r1, u32& r2, u32& r3, u32 addr) {
    asm volatile("ldmatrix.sync.aligned.m8n8.x4.shared.b16 {%0,%1,%2,%3}, [%4];"
                 : "=r"(r0), "=r"(r1), "=r"(r2), "=r"(r3) : "r"(addr));
}
__device__ __forceinline__ void ldsm4t(u32& r0, u32& r1, u32& r2, u32& r3, u32 addr) {
    asm volatile("ldmatrix.sync.aligned.m8n8.x4.trans.shared.b16 {%0,%1,%2,%3}, [%4];"
                 : "=r"(r0), "=r"(r1), "=r"(r2), "=r"(r3) : "r"(addr));
}
__device__ __forceinline__ void mma16816(float* c, u32 a0, u32 a1, u32 a2, u32 a3,
                                          u32 b0, u32 b1) {
    asm volatile("mma.sync.aligned.m16n8k16.row.col.f32.bf16.bf16.f32 "
                 "{%0,%1,%2,%3}, {%4,%5,%6,%7}, {%8,%9}, {%0,%1,%2,%3};"
                 : "+f"(c[0]), "+f"(c[1]), "+f"(c[2]), "+f"(c[3])
                 : "r"(a0), "r"(a1), "r"(a2), "r"(a3), "r"(b0), "r"(b1));
}
__device__ __forceinline__ void split2(float vx, float vy, u32& hi, u32& lo) {
    u32 h; asm("cvt.rn.bf16x2.f32 %0, %1, %2;" : "=r"(h) : "f"(vy), "f"(vx));
    float hx = __uint_as_float(h << 16);
    float hy = __uint_as_float(h & 0xffff0000u);
    u32 l; asm("cvt.rn.bf16x2.f32 %0, %1, %2;" : "=r"(l) : "f"(vy - hy), "f"(vx - hx));
    hi = h; lo = l;
}
__device__ __forceinline__ u16 bf16hi(float v) {
    u16 h; asm("cvt.rn.bf16.f32 %0, %1;" : "=h"(h) : "f"(v)); return h;
}
__device__ __forceinline__ void cp_async16(u32 dst, const void* src, u32 srcsz) {
    asm volatile("cp.async.cg.shared.global [%0], [%1], 16, %2;"
                 :: "r"(dst), "l"(src), "r"(srcsz));
}
__device__ __forceinline__ void cp_commit() { asm volatile("cp.async.commit_group;"); }
__device__ __forceinline__ void cp_wait1() { asm volatile("cp.async.wait_group 1;" ::: "memory"); }
__device__ __forceinline__ void cp_wait0() { asm volatile("cp.async.wait_group 0;" ::: "memory"); }
__device__ __forceinline__ void stcs2(float* p, float2 v) {
    asm volatile("st.global.cs.v2.f32 [%0], {%1,%2};" :: "l"(p), "f"(v.x), "f"(v.y));
}

// ---------------------------------------------------------------------------
// FUSED kernel: weights (2x mma.sync stages) + softmax + reassembly.
// Block = 128 px (2 h-rows of one n), 256 threads, 256 blocks, 2 CTAs/SM.
//
// smem phase 1 (GEMM0):  As_hi/lo [128k][272B], Ws_hi/lo [64oc][272B]
// smem phase 1b (MMA1):  As2 hi/lo, Ws2 hi/lo, L[128][49] (aliased, as R10)
// smem phase 2 (fused):  wts_s[128][40] @0 (20480B, survives),
//                        halo 3 x [16ch][4rows][72f] @20480 (55296B)
// consts @104448.
// ---------------------------------------------------------------------------
#define S_AHI   0
#define S_ALO   34816
#define S_WHI   69632
#define S_WLO   87040
#define S_CST   104448
#define SMEM1   105280

#define S2_AHI  0
#define S2_ALO  17408
#define S2_WHI  34816
#define S2_WLO  47872
#define S2_L    60928

#define S_WTS   0           // 128*40*4 = 20480
#define S_HALO  20480       // 3 * 18432 = 55296 -> ends 75776
#define HALO_B  18432       // 16ch * 4rows * 72f * 4B

extern "C" __global__ void __launch_bounds__(256, 2)
k_fused(const float* __restrict__ x,
        const float* __restrict__ w0, const float* __restrict__ b0,
        const float* __restrict__ bn0_g, const float* __restrict__ bn0_b,
        const float* __restrict__ bn0_m, const float* __restrict__ bn0_v,
        const float* __restrict__ w1, const float* __restrict__ b1,
        const float* __restrict__ bn1_g, const float* __restrict__ bn1_b,
        const float* __restrict__ bn1_m, const float* __restrict__ bn1_v,
        float* __restrict__ out)
{
    extern __shared__ char smem[];
    const u32 sb = smem_u32(smem);
    float* cA0 = (float*)(smem + S_CST);
    float* cB0 = cA0 + 64;
    float* cA1 = cB0 + 64;
    float* cB1 = cA1 + 40;
    float* wts_s = (float*)(smem + S_WTS);
    float* L     = (float*)(smem + S2_L);

    const int t = threadIdx.x;
    const int warp = t >> 5, lane = t & 31;
    const int n = blockIdx.y;
    const int hr = blockIdx.x * 2;          // first h-row of this block
    const int p0 = blockIdx.x * 128;        // flat pixel base

    if (t < 64) {
        float A = bn0_g[t] * rsqrtf(bn0_v[t] + EPS);
        cA0[t] = A;
        cB0[t] = (b0[t] - bn0_m[t]) * A + bn0_b[t];
    } else if (t < 64 + 40) {
        int i = t - 64;
        if (i < Pp) {
            float A = bn1_g[i] * rsqrtf(bn1_v[i] + EPS);
            cA1[i] = A;
            cB1[i] = (b1[i] - bn1_m[i]) * A + bn1_b[i];
        } else { cA1[i] = 0.f; cB1[i] = 0.f; }
    }

    // prefetch w1 into registers
    float2 w1r[5];
    #pragma unroll
    for (int r = 0; r < 5; r++) {
        int i = t + 256 * r;
        w1r[r] = *(const float2*)(w1 + (i >> 5) * OC + (i & 31) * 2);
    }

    const int mat = lane >> 3, mr = lane & 7;
    const int m0 = warp * 16;
    const int g  = lane >> 2, tq = lane & 3;
    const u32 a_off = (u32)((((mat >> 1) * 8) + mr) * 272 + (m0 + (mat & 1) * 8) * 2);
    const u32 b_off = (u32)((((mat >> 1) * 8) + mr) * 272 + (mat & 1) * 16);

    float acc[8][4];
    #pragma unroll
    for (int i = 0; i < 8; i++)
        #pragma unroll
        for (int j = 0; j < 4; j++) acc[i][j] = 0.f;

    // ================= GEMM0: two K-halves =================
    #pragma unroll 1
    for (int h = 0; h < 2; h++) {
        __syncthreads();
        {
            const float4* xr = (const float4*)(x + ((size_t)n * Cc + h * 128 + warp * 16) * HW + p0);
            char* ahb = smem + S_AHI + (warp * 16) * 272 + lane * 8;
            char* alb = smem + S_ALO + (warp * 16) * 272 + lane * 8;
            #pragma unroll 8
            for (int rr = 0; rr < 16; rr++) {
                float4 v = xr[lane];
                u32 h0, l0, h1, l1;
                split2(v.x, v.y, h0, l0);
                split2(v.z, v.w, h1, l1);
                *(uint2*)(ahb) = make_uint2(h0, h1);
                *(uint2*)(alb) = make_uint2(l0, l1);
                xr += HW / 4;
                ahb += 272; alb += 272;
            }
        }
        {
            #pragma unroll 8
            for (int it = 0; it < 8; it++) {
                int oc = it * 8 + warp;
                float4 v = *(const float4*)(w0 + (size_t)oc * Cc + h * 128 + lane * 4);
                u32 h0, l0, h1, l1;
                split2(v.x, v.y, h0, l0);
                split2(v.z, v.w, h1, l1);
                *(uint2*)(smem + S_WHI + oc * 272 + lane * 8) = make_uint2(h0, h1);
                *(uint2*)(smem + S_WLO + oc * 272 + lane * 8) = make_uint2(l0, l1);
            }
        }
        __syncthreads();

        #pragma unroll
        for (int ks = 0; ks < 8; ks++) {
            u32 ah0, ah1, ah2, ah3, al0, al1, al2, al3;
            ldsm4t(ah0, ah1, ah2, ah3, sb + S_AHI + ks * 4352 + a_off);
            ldsm4t(al0, al1, al2, al3, sb + S_ALO + ks * 4352 + a_off);
            #pragma unroll
            for (int j = 0; j < 4; j++) {
                u32 bh0, bh1, bh2, bh3, bl0, bl1, bl2, bl3;
                ldsm4(bh0, bh1, bh2, bh3, sb + S_WHI + j * 16 * 272 + ks * 32 + b_off);
                ldsm4(bl0, bl1, bl2, bl3, sb + S_WLO + j * 16 * 272 + ks * 32 + b_off);
                mma16816(acc[2 * j],     ah0, ah1, ah2, ah3, bh0, bh1);
                mma16816(acc[2 * j],     al0, al1, al2, al3, bh0, bh1);
                mma16816(acc[2 * j],     ah0, ah1, ah2, ah3, bl0, bl1);
                mma16816(acc[2 * j + 1], ah0, ah1, ah2, ah3, bh2, bh3);
                mma16816(acc[2 * j + 1], al0, al1, al2, al3, bh2, bh3);
                mma16816(acc[2 * j + 1], ah0, ah1, ah2, ah3, bl2, bl3);
            }
        }
    }
    __syncthreads();

    // ---- epilogue: BN0 + ReLU -> As2[oc][px] bf16 hi/lo ----
    {
        const int pxa = m0 + g, pxb = m0 + g + 8;
        #pragma unroll
        for (int j = 0; j < 8; j++) {
            int oc0 = 8 * j + 2 * tq, oc1 = oc0 + 1;
            float Aa = cA0[oc0], Ba = cB0[oc0];
            float Ab = cA0[oc1], Bb = cB0[oc1];
            float v00 = fmaxf(fmaf(acc[j][0], Aa, Ba), 0.f);
            float v01 = fmaxf(fmaf(acc[j][1], Ab, Bb), 0.f);
            float v10 = fmaxf(fmaf(acc[j][2], Aa, Ba), 0.f);
            float v11 = fmaxf(fmaf(acc[j][3], Ab, Bb), 0.f);
            #pragma unroll
            for (int q = 0; q < 4; q++) {
                float v  = (q == 0) ? v00 : (q == 1) ? v01 : (q == 2) ? v10 : v11;
                int oc   = (q & 1) ? oc1 : oc0;
                int px   = (q & 2) ? pxb : pxa;
                u16 hi = bf16hi(v);
                float hf = __uint_as_float(((u32)hi) << 16);
                u16 lo = bf16hi(v - hf);
                *(u16*)(smem + S2_AHI + oc * 272 + px * 2) = hi;
                *(u16*)(smem + S2_ALO + oc * 272 + px * 2) = lo;
            }
        }
    }
    // stage Ws2 from w1 regs
    #pragma unroll
    for (int r = 0; r < 5; r++) {
        int i = t + 256 * r;
        int p = i >> 5, oq = i & 31;
        u32 hi, lo;
        split2(w1r[r].x, w1r[r].y, hi, lo);
        *(u32*)(smem + S2_WHI + p * 272 + oq * 4) = hi;
        *(u32*)(smem + S2_WLO + p * 272 + oq * 4) = lo;
    }
    for (int i = t; i < 8 * 68; i += 256) {
        int row = 40 + i / 68, col = i % 68;
        *(u32*)(smem + S2_WHI + row * 272 + col * 4) = 0;
        *(u32*)(smem + S2_WLO + row * 272 + col * 4) = 0;
    }
    __syncthreads();

    // ================= MMA1: logits [128, 40] =================
    float d1[5][4];
    #pragma unroll
    for (int i = 0; i < 5; i++)
        #pragma unroll
        for (int j = 0; j < 4; j++) d1[i][j] = 0.f;

    #pragma unroll
    for (int ks = 0; ks < 4; ks++) {
        u32 ah0, ah1, ah2, ah3, al0, al1, al2, al3;
        ldsm4t(ah0, ah1, ah2, ah3, sb + S2_AHI + ks * 4352 + a_off);
        ldsm4t(al0, al1, al2, al3, sb + S2_ALO + ks * 4352 + a_off);
        #pragma unroll
        for (int rb = 0; rb < 3; rb++) {
            u32 bh0, bh1, bh2, bh3, bl0, bl1, bl2, bl3;
            ldsm4(bh0, bh1, bh2, bh3, sb + S2_WHI + rb * 4352 + ks * 32 + b_off);
            ldsm4(bl0, bl1, bl2, bl3, sb + S2_WLO + rb * 4352 + ks * 32 + b_off);
            int nt = 2 * rb;
            mma16816(d1[nt], ah0, ah1, ah2, ah3, bh0, bh1);
            mma16816(d1[nt], al0, al1, al2, al3, bh0, bh1);
            mma16816(d1[nt], ah0, ah1, ah2, ah3, bl0, bl1);
            if (rb < 2) {
                mma16816(d1[nt + 1], ah0, ah1, ah2, ah3, bh2, bh3);
                mma16816(d1[nt + 1], al0, al1, al2, al3, bh2, bh3);
                mma16816(d1[nt + 1], ah0, ah1, ah2, ah3, bl2, bl3);
            }
        }
    }
    #pragma unroll
    for (int nt = 0; nt < 5; nt++) {
        int pc0 = 8 * nt + 2 * tq, pc1 = pc0 + 1;
        float Aa = cA1[pc0], Ba = cB1[pc0];
        float Ab = cA1[pc1], Bb = cB1[pc1];
        L[(m0 + g) * 49 + pc0]     = fmaxf(fmaf(d1[nt][0], Aa, Ba), 0.f);
        L[(m0 + g) * 49 + pc1]     = fmaxf(fmaf(d1[nt][1], Ab, Bb), 0.f);
        L[(m0 + g + 8) * 49 + pc0] = fmaxf(fmaf(d1[nt][2], Aa, Ba), 0.f);
        L[(m0 + g + 8) * 49 + pc1] = fmaxf(fmaf(d1[nt][3], Ab, Bb), 0.f);
    }
    __syncthreads();

    // ---- softmax over k (9) for u = hh, hh+2 -> wts_s[px][40] ----
    {
        const int px = t & 127;
        const int hh = t >> 7;
        const float* Lp = L + px * 49;
        #pragma unroll
        for (int uu = 0; uu < 2; uu++) {
            int u = hh + 2 * uu;
            float e[9], mx = -1e30f;
            #pragma unroll
            for (int k = 0; k < 9; k++) { e[k] = Lp[k * 4 + u]; mx = fmaxf(mx, e[k]); }
            float s = 0.f;
            #pragma unroll
            for (int k = 0; k < 9; k++) { float q = __expf(e[k] - mx); e[k] = q; s += q; }
            float inv = 1.f / s;
            #pragma unroll
            for (int k = 0; k < 9; k++) wts_s[px * 40 + k * 4 + u] = e[k] * inv;
        }
    }
    __syncthreads();   // wts_s complete; L/Ws2 regions dead -> halo may reuse

    // ================= PHASE 2: reassembly for this block's 2 h-rows =======
    // loader geometry: 1152 float4 per chunk = 16ch x 4rows x 18vec
    const float* xb = x + (size_t)n * Cc * HW;
    u32  smOff[5];
    int  gOff[5];
    bool pred[5], act[5];
    #pragma unroll
    for (int i = 0; i < 5; i++) {
        int idx = i * 256 + t;
        act[i] = idx < 1152;
        int ch  = idx / 72;
        int rem = idx - ch * 72;
        int row = rem / 18, j = rem - row * 18;
        bool rok = ((unsigned)(hr - 1 + row) < (unsigned)Hh);
        bool cok = (j >= 1) && (j <= 16);
        pred[i]  = act[i] && rok && cok;
        smOff[i] = (u32)(S_HALO + ((ch * 4 + row) * 72 + 4 * j) * 4);
        gOff[i]  = ch * HW + (hr - 1 + row) * Ww + (4 * j - 4);
    }

    // prefetch chunks 0,1
    #pragma unroll
    for (int c = 0; c < 2; c++) {
        const float* gch = xb + (size_t)c * 16 * HW;
        u32 sb2 = sb + c * HALO_B;
        #pragma unroll
        for (int i = 0; i < 5; i++)
            if (act[i]) cp_async16(sb2 + smOff[i], pred[i] ? gch + gOff[i] : xb,
                                   pred[i] ? 16u : 0u);
        cp_commit();
    }

    // weights -> registers: 9 x LDS.128 (stride 40 => 16B aligned)
    const int px   = t & 127;
    const int half = t >> 7;          // channel half within each chunk
    const int r    = px >> 6;         // row within block (0/1)
    const int w    = px & 63;
    u64 wp01[9], wp23[9];
    {
        const float4* wpp = (const float4*)(wts_s + px * 40);
        #pragma unroll
        for (int k = 0; k < 9; k++) {
            float4 v = wpp[k];
            wp01[k] = pack2(v.x, v.y);
            wp23[k] = pack2(v.z, v.w);
        }
    }

    const float* xsf = (const float*)(smem + S_HALO);
    float* opb = out + ((size_t)(n * Cc + half * 8) * HW) * 4
                     + (2 * (hr + r)) * 128 + 2 * w;

    #pragma unroll 1
    for (int ch16 = 0; ch16 < 16; ch16++) {
        if (ch16 == 15) cp_wait0(); else cp_wait1();
        __syncthreads();

        if (ch16 < 14) {
            const float* gch = xb + (size_t)(ch16 + 2) * 16 * HW;
            u32 sb2 = sb + ((ch16 + 2) % 3) * HALO_B;
            #pragma unroll
            for (int i = 0; i < 5; i++)
                if (act[i]) cp_async16(sb2 + smOff[i], pred[i] ? gch + gOff[i] : xb,
                                       pred[i] ? 16u : 0u);
            cp_commit();
        }

        const float* xc = xsf + ((ch16 % 3) * HALO_B) / 4 + (half * 8) * 288 + r * 72 + w + 3;
        float* op = opb + (size_t)ch16 * 16 * (HW * 4);
        #pragma unroll
        for (int j = 0; j < 8; j++) {
            u64 a01 = 0ULL, a23 = 0ULL;
            #pragma unroll
            for (int dy = 0; dy < 3; dy++) {
                const float* rr = xc + j * 288 + dy * 72;
                #pragma unroll
                for (int dx = 0; dx < 3; dx++) {
                    float xv = rr[dx];
                    u64 xp = pack2(xv, xv);
                    int k = dy * 3 + dx;
                    fma2(a01, xp, wp01[k]);
                    fma2(a23, xp, wp23[k]);
                }
            }
            stcs2(op,       unpack2(a01));
            stcs2(op + 128, unpack2(a23));
            op += HW * 4;
        }
    }
}

extern "C" void kernel_launch(void* const* d_in, const int* in_sizes, int n_in,
                              void* d_out, int out_size)
{
    const float* x     = (const float*)d_in[0];
    const float* w0    = (const float*)d_in[1];
    const float* b0    = (const float*)d_in[2];
    const float* bn0_g = (const float*)d_in[3];
    const float* bn0_b = (const float*)d_in[4];
    const float* bn0_m = (const float*)d_in[5];
    const float* bn0_v = (const float*)d_in[6];
    const float* w1    = (const float*)d_in[7];
    const float* b1    = (const float*)d_in[8];
    const float* bn1_g = (const float*)d_in[9];
    const float* bn1_b = (const float*)d_in[10];
    const float* bn1_m = (const float*)d_in[11];
    const float* bn1_v = (const float*)d_in[12];
    float* out = (float*)d_out;

    cudaFuncSetAttribute(k_fused, cudaFuncAttributeMaxDynamicSharedMemorySize, SMEM1);
    dim3 g1(32, Nn);
    k_fused<<<g1, 256, SMEM1>>>(x, w0, b0, bn0_g, bn0_b, bn0_m, bn0_v,
                                w1, b1, bn1_g, bn1_b, bn1_m, bn1_v, out);
}

// round 14
// speedup vs baseline: 1.0863x; 1.0863x over previous
#include <cuda_runtime.h>
#include <cstdint>

#define EPS 1e-5f
#define Nn 8
#define Cc 256
#define Hh 64
#define Ww 64
#define HW 4096
#define OC 64
#define Pp 36

typedef unsigned long long u64;
typedef unsigned int u32;
typedef unsigned short u16;

// softmax weights scratch, layout [n][h][36][w] (w contiguous)
__device__ float g_wts[(size_t)Nn * HW * Pp];

__device__ __forceinline__ u64 pack2(float x, float y) {
    u64 r; asm("mov.b64 %0, {%1,%2};" : "=l"(r) : "f"(x), "f"(y)); return r;
}
__device__ __forceinline__ void fma2(u64 &d, u64 a, u64 b) {
    asm("fma.rn.f32x2 %0, %1, %2, %0;" : "+l"(d) : "l"(a), "l"(b));
}
__device__ __forceinline__ float2 unpack2(u64 v) {
    float2 r; asm("mov.b64 {%0,%1}, %2;" : "=f"(r.x), "=f"(r.y) : "l"(v)); return r;
}
__device__ __forceinline__ u32 smem_u32(const void* p) {
    u32 a;
    asm("{ .reg .u64 t; cvta.to.shared.u64 t, %1; cvt.u32.u64 %0, t; }" : "=r"(a) : "l"(p));
    return a;
}
__device__ __forceinline__ void ldsm4(u32& r0, u32& r1, u32& r2, u32& r3, u32 addr) {
    asm volatile("ldmatrix.sync.aligned.m8n8.x4.shared.b16 {%0,%1,%2,%3}, [%4];"
                 : "=r"(r0), "=r"(r1), "=r"(r2), "=r"(r3) : "r"(addr));
}
__device__ __forceinline__ void ldsm4t(u32& r0, u32& r1, u32& r2, u32& r3, u32 addr) {
    asm volatile("ldmatrix.sync.aligned.m8n8.x4.trans.shared.b16 {%0,%1,%2,%3}, [%4];"
                 : "=r"(r0), "=r"(r1), "=r"(r2), "=r"(r3) : "r"(addr));
}
__device__ __forceinline__ void mma16816(float* c, u32 a0, u32 a1, u32 a2, u32 a3,
                                          u32 b0, u32 b1) {
    asm volatile("mma.sync.aligned.m16n8k16.row.col.f32.bf16.bf16.f32 "
                 "{%0,%1,%2,%3}, {%4,%5,%6,%7}, {%8,%9}, {%0,%1,%2,%3};"
                 : "+f"(c[0]), "+f"(c[1]), "+f"(c[2]), "+f"(c[3])
                 : "r"(a0), "r"(a1), "r"(a2), "r"(a3), "r"(b0), "r"(b1));
}
__device__ __forceinline__ void split2(float vx, float vy, u32& hi, u32& lo) {
    u32 h; asm("cvt.rn.bf16x2.f32 %0, %1, %2;" : "=r"(h) : "f"(vy), "f"(vx));
    float hx = __uint_as_float(h << 16);
    float hy = __uint_as_float(h & 0xffff0000u);
    u32 l; asm("cvt.rn.bf16x2.f32 %0, %1, %2;" : "=r"(l) : "f"(vy - hy), "f"(vx - hx));
    hi = h; lo = l;
}
__device__ __forceinline__ u16 bf16hi(float v) {
    u16 h; asm("cvt.rn.bf16.f32 %0, %1;" : "=h"(h) : "f"(v)); return h;
}

// ---------------------------------------------------------------------------
// Kernel 1: weights. GEMM0 + encoder on mma.sync (R10 body; dump [n][h][36][w]).
// ---------------------------------------------------------------------------
#define S_AHI   0
#define S_ALO   34816
#define S_WHI   69632
#define S_WLO   87040
#define S_CST   104448
#define SMEM1   105280

#define S2_AHI  0
#define S2_ALO  17408
#define S2_WHI  34816
#define S2_WLO  47872
#define S2_L    60928
#define S2_WTS  0

extern "C" __global__ void __launch_bounds__(256, 2)
k_weights(const float* __restrict__ x,
          const float* __restrict__ w0, const float* __restrict__ b0,
          const float* __restrict__ bn0_g, const float* __restrict__ bn0_b,
          const float* __restrict__ bn0_m, const float* __restrict__ bn0_v,
          const float* __restrict__ w1, const float* __restrict__ b1,
          const float* __restrict__ bn1_g, const float* __restrict__ bn1_b,
          const float* __restrict__ bn1_m, const float* __restrict__ bn1_v)
{
    extern __shared__ char smem[];
    const u32 sb = smem_u32(smem);
    float* cA0 = (float*)(smem + S_CST);
    float* cB0 = cA0 + 64;
    float* cA1 = cB0 + 64;
    float* cB1 = cA1 + 40;
    float* wts_s = (float*)(smem + S2_WTS);
    float* L     = (float*)(smem + S2_L);

    const int t = threadIdx.x;
    const int warp = t >> 5, lane = t & 31;
    const int n = blockIdx.y, p0 = blockIdx.x * 128;

    if (t < 64) {
        float A = bn0_g[t] * rsqrtf(bn0_v[t] + EPS);
        cA0[t] = A;
        cB0[t] = (b0[t] - bn0_m[t]) * A + bn0_b[t];
    } else if (t < 64 + 40) {
        int i = t - 64;
        if (i < Pp) {
            float A = bn1_g[i] * rsqrtf(bn1_v[i] + EPS);
            cA1[i] = A;
            cB1[i] = (b1[i] - bn1_m[i]) * A + bn1_b[i];
        } else { cA1[i] = 0.f; cB1[i] = 0.f; }
    }

    float2 w1r[5];
    #pragma unroll
    for (int r = 0; r < 5; r++) {
        int i = t + 256 * r;
        w1r[r] = *(const float2*)(w1 + (i >> 5) * OC + (i & 31) * 2);
    }

    const int mat = lane >> 3, mr = lane & 7;
    const int m0 = warp * 16;
    const int g  = lane >> 2, tq = lane & 3;
    const u32 a_off = (u32)((((mat >> 1) * 8) + mr) * 272 + (m0 + (mat & 1) * 8) * 2);
    const u32 b_off = (u32)((((mat >> 1) * 8) + mr) * 272 + (mat & 1) * 16);

    float acc[8][4];
    #pragma unroll
    for (int i = 0; i < 8; i++)
        #pragma unroll
        for (int j = 0; j < 4; j++) acc[i][j] = 0.f;

    #pragma unroll 1
    for (int h = 0; h < 2; h++) {
        __syncthreads();
        {
            const float4* xr = (const float4*)(x + ((size_t)n * Cc + h * 128 + warp * 16) * HW + p0);
            char* ahb = smem + S_AHI + (warp * 16) * 272 + lane * 8;
            char* alb = smem + S_ALO + (warp * 16) * 272 + lane * 8;
            #pragma unroll 8
            for (int rr = 0; rr < 16; rr++) {
                float4 v = xr[lane];
                u32 h0, l0, h1, l1;
                split2(v.x, v.y, h0, l0);
                split2(v.z, v.w, h1, l1);
                *(uint2*)(ahb) = make_uint2(h0, h1);
                *(uint2*)(alb) = make_uint2(l0, l1);
                xr += HW / 4;
                ahb += 272; alb += 272;
            }
        }
        {
            #pragma unroll 8
            for (int it = 0; it < 8; it++) {
                int oc = it * 8 + warp;
                float4 v = *(const float4*)(w0 + (size_t)oc * Cc + h * 128 + lane * 4);
                u32 h0, l0, h1, l1;
                split2(v.x, v.y, h0, l0);
                split2(v.z, v.w, h1, l1);
                *(uint2*)(smem + S_WHI + oc * 272 + lane * 8) = make_uint2(h0, h1);
                *(uint2*)(smem + S_WLO + oc * 272 + lane * 8) = make_uint2(l0, l1);
            }
        }
        __syncthreads();

        #pragma unroll
        for (int ks = 0; ks < 8; ks++) {
            u32 ah0, ah1, ah2, ah3, al0, al1, al2, al3;
            ldsm4t(ah0, ah1, ah2, ah3, sb + S_AHI + ks * 4352 + a_off);
            ldsm4t(al0, al1, al2, al3, sb + S_ALO + ks * 4352 + a_off);
            #pragma unroll
            for (int j = 0; j < 4; j++) {
                u32 bh0, bh1, bh2, bh3, bl0, bl1, bl2, bl3;
                ldsm4(bh0, bh1, bh2, bh3, sb + S_WHI + j * 16 * 272 + ks * 32 + b_off);
                ldsm4(bl0, bl1, bl2, bl3, sb + S_WLO + j * 16 * 272 + ks * 32 + b_off);
                mma16816(acc[2 * j],     ah0, ah1, ah2, ah3, bh0, bh1);
                mma16816(acc[2 * j],     al0, al1, al2, al3, bh0, bh1);
                mma16816(acc[2 * j],     ah0, ah1, ah2, ah3, bl0, bl1);
                mma16816(acc[2 * j + 1], ah0, ah1, ah2, ah3, bh2, bh3);
                mma16816(acc[2 * j + 1], al0, al1, al2, al3, bh2, bh3);
                mma16816(acc[2 * j + 1], ah0, ah1, ah2, ah3, bl2, bl3);
            }
        }
    }
    __syncthreads();

    {
        const int pxa = m0 + g, pxb = m0 + g + 8;
        #pragma unroll
        for (int j = 0; j < 8; j++) {
            int oc0 = 8 * j + 2 * tq, oc1 = oc0 + 1;
            float Aa = cA0[oc0], Ba = cB0[oc0];
            float Ab = cA0[oc1], Bb = cB0[oc1];
            float v00 = fmaxf(fmaf(acc[j][0], Aa, Ba), 0.f);
            float v01 = fmaxf(fmaf(acc[j][1], Ab, Bb), 0.f);
            float v10 = fmaxf(fmaf(acc[j][2], Aa, Ba), 0.f);
            float v11 = fmaxf(fmaf(acc[j][3], Ab, Bb), 0.f);
            #pragma unroll
            for (int q = 0; q < 4; q++) {
                float v  = (q == 0) ? v00 : (q == 1) ? v01 : (q == 2) ? v10 : v11;
                int oc   = (q & 1) ? oc1 : oc0;
                int px   = (q & 2) ? pxb : pxa;
                u16 hi = bf16hi(v);
                float hf = __uint_as_float(((u32)hi) << 16);
                u16 lo = bf16hi(v - hf);
                *(u16*)(smem + S2_AHI + oc * 272 + px * 2) = hi;
                *(u16*)(smem + S2_ALO + oc * 272 + px * 2) = lo;
            }
        }
    }
    #pragma unroll
    for (int r = 0; r < 5; r++) {
        int i = t + 256 * r;
        int p = i >> 5, oq = i & 31;
        u32 hi, lo;
        split2(w1r[r].x, w1r[r].y, hi, lo);
        *(u32*)(smem + S2_WHI + p * 272 + oq * 4) = hi;
        *(u32*)(smem + S2_WLO + p * 272 + oq * 4) = lo;
    }
    for (int i = t; i < 8 * 68; i += 256) {
        int row = 40 + i / 68, col = i % 68;
        *(u32*)(smem + S2_WHI + row * 272 + col * 4) = 0;
        *(u32*)(smem + S2_WLO + row * 272 + col * 4) = 0;
    }
    __syncthreads();

    float d1[5][4];
    #pragma unroll
    for (int i = 0; i < 5; i++)
        #pragma unroll
        for (int j = 0; j < 4; j++) d1[i][j] = 0.f;

    #pragma unroll
    for (int ks = 0; ks < 4; ks++) {
        u32 ah0, ah1, ah2, ah3, al0, al1, al2, al3;
        ldsm4t(ah0, ah1, ah2, ah3, sb + S2_AHI + ks * 4352 + a_off);
        ldsm4t(al0, al1, al2, al3, sb + S2_ALO + ks * 4352 + a_off);
        #pragma unroll
        for (int rb = 0; rb < 3; rb++) {
            u32 bh0, bh1, bh2, bh3, bl0, bl1, bl2, bl3;
            ldsm4(bh0, bh1, bh2, bh3, sb + S2_WHI + rb * 4352 + ks * 32 + b_off);
            ldsm4(bl0, bl1, bl2, bl3, sb + S2_WLO + rb * 4352 + ks * 32 + b_off);
            int nt = 2 * rb;
            mma16816(d1[nt], ah0, ah1, ah2, ah3, bh0, bh1);
            mma16816(d1[nt], al0, al1, al2, al3, bh0, bh1);
            mma16816(d1[nt], ah0, ah1, ah2, ah3, bl0, bl1);
            if (rb < 2) {
                mma16816(d1[nt + 1], ah0, ah1, ah2, ah3, bh2, bh3);
                mma16816(d1[nt + 1], al0, al1, al2, al3, bh2, bh3);
                mma16816(d1[nt + 1], ah0, ah1, ah2, ah3, bl2, bl3);
            }
        }
    }
    #pragma unroll
    for (int nt = 0; nt < 5; nt++) {
        int pc0 = 8 * nt + 2 * tq, pc1 = pc0 + 1;
        float Aa = cA1[pc0], Ba = cB1[pc0];
        float Ab = cA1[pc1], Bb = cB1[pc1];
        L[(m0 + g) * 49 + pc0]     = fmaxf(fmaf(d1[nt][0], Aa, Ba), 0.f);
        L[(m0 + g) * 49 + pc1]     = fmaxf(fmaf(d1[nt][1], Ab, Bb), 0.f);
        L[(m0 + g + 8) * 49 + pc0] = fmaxf(fmaf(d1[nt][2], Aa, Ba), 0.f);
        L[(m0 + g + 8) * 49 + pc1] = fmaxf(fmaf(d1[nt][3], Ab, Bb), 0.f);
    }
    __syncthreads();

    {
        const int px = t & 127;
        const int hh = t >> 7;
        const float* Lp = L + px * 49;
        #pragma unroll
        for (int uu = 0; uu < 2; uu++) {
            int u = hh + 2 * uu;
            float e[9], mx = -1e30f;
            #pragma unroll
            for (int k = 0; k < 9; k++) { e[k] = Lp[k * 4 + u]; mx = fmaxf(mx, e[k]); }
            float s = 0.f;
            #pragma unroll
            for (int k = 0; k < 9; k++) { float q = __expf(e[k] - mx); e[k] = q; s += q; }
            float inv = 1.f / s;
            #pragma unroll
            for (int k = 0; k < 9; k++) wts_s[px * 37 + k * 4 + u] = e[k] * inv;
        }
    }
    __syncthreads();

    {
        const int hrow = p0 >> 6;
        float* gb = g_wts + (size_t)(n * Hh + hrow) * (36 * 64);
        for (int i = t; i < 2 * 36 * 64; i += 256) {
            int w = i & 63;
            int c = (i >> 6) % 36;
            int r = i / (36 * 64);
            gb[(size_t)(r * 36 + c) * 64 + w] = wts_s[(r * 64 + w) * 37 + c];
        }
    }
}

// ---------------------------------------------------------------------------
// Kernel 2: reassembly, 2 px/thread -> STG.128 + LDS.64 taps.
// Block: 8 h-rows x full 64-px width, 64 channels (c-split 4). 256 threads.
// Dynamic smem: 3 x [8ch][10rows][72f] = 69120 B.
// ---------------------------------------------------------------------------
__device__ __forceinline__ void cp_async16(u32 dst, const void* src, u32 srcsz) {
    asm volatile("cp.async.cg.shared.global [%0], [%1], 16, %2;"
                 :: "r"(dst), "l"(src), "r"(srcsz));
}
__device__ __forceinline__ void cp_commit() { asm volatile("cp.async.commit_group;"); }
__device__ __forceinline__ void cp_wait1() { asm volatile("cp.async.wait_group 1;" ::: "memory"); }
__device__ __forceinline__ void cp_wait0() { asm volatile("cp.async.wait_group 0;" ::: "memory"); }
__device__ __forceinline__ void stcs4(float* p, float4 v) {
    asm volatile("st.global.cs.v4.f32 [%0], {%1,%2,%3,%4};"
                 :: "l"(p), "f"(v.x), "f"(v.y), "f"(v.z), "f"(v.w));
}

#define ROWF2    72
#define CHUNK2_B (8 * 10 * ROWF2 * 4)    // 23040
#define SMEM2    (3 * CHUNK2_B)          // 69120

extern "C" __global__ void __launch_bounds__(256, 2)
k_reassemble(const float* __restrict__ x, float* __restrict__ out)
{
    extern __shared__ float xsf[];
    const u32 s_base = smem_u32(xsf);

    const int tid = threadIdx.x;
    const int tx  = tid & 31;           // pixel pair index: px = 2tx, 2tx+1
    const int ty  = tid >> 5;           // h row within tile
    const int h0  = blockIdx.x * 8;
    const int n   = blockIdx.y >> 2;
    const int c0  = (blockIdx.y & 3) * 64;
    const int h   = h0 + ty;

    const float* xb = x + (size_t)n * Cc * HW;

    // ---- hoisted loader: 1440 vec4 per chunk = 8ch x 10rows x 18vec ----
    u32  smOff[6];
    int  gOff[6];
    bool pred[6], act[6];
    #pragma unroll
    for (int i = 0; i < 6; i++) {
        int idx = i * 256 + tid;
        act[i] = idx < 1440;
        int ch  = idx / 180;
        int rem = idx - ch * 180;
        int row = rem / 18, j = rem - row * 18;
        bool rok = ((unsigned)(h0 - 1 + row) < (unsigned)Hh);
        bool cok = (j >= 1) && (j <= 16);
        pred[i]  = act[i] && rok && cok;
        smOff[i] = (u32)(((ch * 10 + row) * ROWF2 + 4 * j) * 4);
        gOff[i]  = ch * HW + (h0 - 1 + row) * Ww + (4 * j - 4);
    }

    // prefetch chunks 0,1 (channels c0.. and c0+8..)
    #pragma unroll
    for (int c = 0; c < 2; c++) {
        const float* gch = xb + (size_t)(c0 + c * 8) * HW;
        u32 sb2 = s_base + c * CHUNK2_B;
        #pragma unroll
        for (int i = 0; i < 6; i++)
            if (act[i]) cp_async16(sb2 + smOff[i], pred[i] ? gch + gOff[i] : xb,
                                   pred[i] ? 16u : 0u);
        cp_commit();
    }

    // ---- weights: cross-pixel packed pairs wk[k][u] = (w[c][2tx], w[c][2tx+1]) ----
    u64 wk[9][4];
    {
        const float2* wb2 = (const float2*)(g_wts + (size_t)(n * Hh + h) * (36 * 64));
        #pragma unroll
        for (int k = 0; k < 9; k++)
            #pragma unroll
            for (int u = 0; u < 4; u++) {
                float2 v = __ldg(wb2 + (k * 4 + u) * 32 + tx);
                wk[k][u] = pack2(v.x, v.y);
            }
    }

    // output base: row 2h, cols 4tx..4tx+3
    float* opb = out + ((size_t)(n * Cc + c0) * HW) * 4 + (2 * h) * 128 + 4 * tx;

    #pragma unroll 1
    for (int ch8 = 0; ch8 < 8; ch8++) {
        if (ch8 == 7) cp_wait0(); else cp_wait1();
        __syncthreads();

        if (ch8 < 6) {
            const float* gch = xb + (size_t)(c0 + (ch8 + 2) * 8) * HW;
            u32 sb2 = s_base + ((ch8 + 2) % 3) * CHUNK2_B;
            #pragma unroll
            for (int i = 0; i < 6; i++)
                if (act[i]) cp_async16(sb2 + smOff[i], pred[i] ? gch + gOff[i] : xb,
                                       pred[i] ? 16u : 0u);
            cp_commit();
        }

        const float* bufp = xsf + ((ch8 % 3) * CHUNK2_B) / 4 + ty * ROWF2 + 2 * tx + 2;
        float* op = opb + (size_t)ch8 * 8 * (HW * 4);
        #pragma unroll
        for (int cl = 0; cl < 8; cl++) {
            const float* rowp = bufp + cl * 10 * ROWF2;
            u64 a0 = 0ULL, a1 = 0ULL, a2 = 0ULL, a3 = 0ULL;
            #pragma unroll
            for (int dy = 0; dy < 3; dy++) {
                const float* rp = rowp + dy * ROWF2;
                u64 t0 = *(const u64*)(rp);        // cols 2tx+2, 2tx+3
                u64 t1 = *(const u64*)(rp + 2);    // cols 2tx+4, 2tx+5
                u64 t2 = *(const u64*)(rp + 4);    // cols 2tx+6, 2tx+7
                float2 f0 = unpack2(t0);
                float2 f1 = unpack2(t1);
                float2 f2 = unpack2(t2);
                u64 xp0 = pack2(f0.y, f1.x);       // taps dx=0: (px0, px1)
                u64 xp1 = t1;                      // taps dx=1
                u64 xp2 = pack2(f1.y, f2.x);       // taps dx=2
                int k = dy * 3;
                fma2(a0, xp0, wk[k][0]); fma2(a1, xp0, wk[k][1]);
                fma2(a2, xp0, wk[k][2]); fma2(a3, xp0, wk[k][3]);
                fma2(a0, xp1, wk[k + 1][0]); fma2(a1, xp1, wk[k + 1][1]);
                fma2(a2, xp1, wk[k + 1][2]); fma2(a3, xp1, wk[k + 1][3]);
                fma2(a0, xp2, wk[k + 2][0]); fma2(a1, xp2, wk[k + 2][1]);
                fma2(a2, xp2, wk[k + 2][2]); fma2(a3, xp2, wk[k + 2][3]);
            }
            float2 r0 = unpack2(a0), r1 = unpack2(a1);
            float2 r2 = unpack2(a2), r3 = unpack2(a3);
            stcs4(op,       make_float4(r0.x, r1.x, r0.y, r1.y));   // row 2h
            stcs4(op + 128, make_float4(r2.x, r3.x, r2.y, r3.y));   // row 2h+1
            op += HW * 4;
        }
    }
}

extern "C" void kernel_launch(void* const* d_in, const int* in_sizes, int n_in,
                              void* d_out, int out_size)
{
    const float* x     = (const float*)d_in[0];
    const float* w0    = (const float*)d_in[1];
    const float* b0    = (const float*)d_in[2];
    const float* bn0_g = (const float*)d_in[3];
    const float* bn0_b = (const float*)d_in[4];
    const float* bn0_m = (const float*)d_in[5];
    const float* bn0_v = (const float*)d_in[6];
    const float* w1    = (const float*)d_in[7];
    const float* b1    = (const float*)d_in[8];
    const float* bn1_g = (const float*)d_in[9];
    const float* bn1_b = (const float*)d_in[10];
    const float* bn1_m = (const float*)d_in[11];
    const float* bn1_v = (const float*)d_in[12];
    float* out = (float*)d_out;

    cudaFuncSetAttribute(k_weights, cudaFuncAttributeMaxDynamicSharedMemorySize, SMEM1);
    cudaFuncSetAttribute(k_reassemble, cudaFuncAttributeMaxDynamicSharedMemorySize, SMEM2);

    dim3 g1(32, Nn);
    k_weights<<<g1, 256, SMEM1>>>(x, w0, b0, bn0_g, bn0_b, bn0_m, bn0_v,
                                  w1, b1, bn1_g, bn1_b, bn1_m, bn1_v);

    dim3 g2(8, Nn * 4);
    k_reassemble<<<g2, 256, SMEM2>>>(x, out);
}